// round 4
// baseline (speedup 1.0000x reference)
#include <cuda_runtime.h>
#include <math.h>
#include <stdint.h>

#define B 128
#define T 512
#define E 256
#define H 256
#define DA 25
#define HEADS 5
#define V 2080

typedef unsigned long long ull;

// ---------------- device scratch (static, no allocs) ----------------
__device__ float g_P[(size_t)2 * V * 1024];        // [dir][v][4H]  17MB (L2-resident)
__device__ ull   g_hdup[2 * 2 * B * 256];          // [buf][dir][b][j] as (h,h) pairs, 1MB
__device__ float g_Hc[(size_t)B * T * 2 * H];      // [b][t][512]  128MB (tail never read w/ nonzero A)
__device__ float g_s[B * HEADS * T];               // [b][h][t]
__device__ float g_A[B * HEADS * T];               // [b][h][t]
__device__ float g_pp[B];
__device__ unsigned g_bar[8];

__device__ __forceinline__ float sigf(float x) { return 1.0f / (1.0f + expf(-x)); }

__device__ __forceinline__ ull pack2(float lo, float hi) {
    ull r; asm("mov.b64 %0, {%1,%2};" : "=l"(r) : "f"(lo), "f"(hi)); return r;
}
__device__ __forceinline__ void unpack2(ull v, float& lo, float& hi) {
    asm("mov.b64 {%0,%1}, %2;" : "=f"(lo), "=f"(hi) : "l"(v));
}
__device__ __forceinline__ ull fma2(ull a, ull b, ull c) {
    ull d; asm("fma.rn.f32x2 %0, %1, %2, %3;" : "=l"(d) : "l"(a), "l"(b), "l"(c)); return d;
}
__device__ __forceinline__ ull add2(ull a, ull b) {
    ull d; asm("add.rn.f32x2 %0, %1, %2;" : "=l"(d) : "l"(a), "l"(b)); return d;
}

// ---------------- init: zero h buffers + barriers --------------------
__global__ void k_init() {
    size_t i = (size_t)blockIdx.x * blockDim.x + threadIdx.x;
    size_t stride = (size_t)gridDim.x * blockDim.x;
    for (size_t p = i; p < (size_t)2 * 2 * B * 256; p += stride) g_hdup[p] = 0ull;
    if (i < 8) g_bar[i] = 0u;
}

// ---------------- vocab projection: P[d][v][n] = emb[v] . W_ih[n] + b[n]
__global__ void k_P(const float* __restrict__ emb,
                    const float* __restrict__ Wf, const float* __restrict__ bf,
                    const float* __restrict__ Wb, const float* __restrict__ bb)
{
    const int d = blockIdx.z;
    const float* __restrict__ Wih  = d ? Wb : Wf;
    const float* __restrict__ bias = d ? bb : bf;
    const int n0 = blockIdx.x * 64;
    const int m0 = blockIdx.y * 64;

    __shared__ float As[16][68];
    __shared__ float Bs[16][68];

    const int tid = threadIdx.x;
    const int r  = tid >> 2, kq = tid & 3;
    const int tx = tid & 15, ty = tid >> 4;
    int v = m0 + r; if (v >= V) v = 0;
    const float* __restrict__ Arow = emb + (size_t)v * E;
    const float* __restrict__ Brow = Wih + (size_t)(n0 + r) * E;

    float acc[4][4] = {};

    for (int k0 = 0; k0 < E; k0 += 16) {
        float4 av = *(const float4*)&Arow[k0 + kq * 4];
        float4 bv = *(const float4*)&Brow[k0 + kq * 4];
        As[kq * 4 + 0][r] = av.x; As[kq * 4 + 1][r] = av.y;
        As[kq * 4 + 2][r] = av.z; As[kq * 4 + 3][r] = av.w;
        Bs[kq * 4 + 0][r] = bv.x; Bs[kq * 4 + 1][r] = bv.y;
        Bs[kq * 4 + 2][r] = bv.z; Bs[kq * 4 + 3][r] = bv.w;
        __syncthreads();
        #pragma unroll
        for (int kk = 0; kk < 16; kk++) {
            float4 a  = *(const float4*)&As[kk][ty * 4];
            float4 b4 = *(const float4*)&Bs[kk][tx * 4];
            acc[0][0] = fmaf(a.x, b4.x, acc[0][0]); acc[0][1] = fmaf(a.x, b4.y, acc[0][1]);
            acc[0][2] = fmaf(a.x, b4.z, acc[0][2]); acc[0][3] = fmaf(a.x, b4.w, acc[0][3]);
            acc[1][0] = fmaf(a.y, b4.x, acc[1][0]); acc[1][1] = fmaf(a.y, b4.y, acc[1][1]);
            acc[1][2] = fmaf(a.y, b4.z, acc[1][2]); acc[1][3] = fmaf(a.y, b4.w, acc[1][3]);
            acc[2][0] = fmaf(a.z, b4.x, acc[2][0]); acc[2][1] = fmaf(a.z, b4.y, acc[2][1]);
            acc[2][2] = fmaf(a.z, b4.z, acc[2][2]); acc[2][3] = fmaf(a.z, b4.w, acc[2][3]);
            acc[3][0] = fmaf(a.w, b4.x, acc[3][0]); acc[3][1] = fmaf(a.w, b4.y, acc[3][1]);
            acc[3][2] = fmaf(a.w, b4.z, acc[3][2]); acc[3][3] = fmaf(a.w, b4.w, acc[3][3]);
        }
        __syncthreads();
    }

    float b0v = bias[n0 + tx * 4 + 0];
    float b1v = bias[n0 + tx * 4 + 1];
    float b2v = bias[n0 + tx * 4 + 2];
    float b3v = bias[n0 + tx * 4 + 3];
    const size_t pbase = (size_t)d * V * 1024;
    #pragma unroll
    for (int i = 0; i < 4; i++) {
        int m = m0 + ty * 4 + i;
        if (m < V) {
            float4 o;
            o.x = acc[i][0] + b0v; o.y = acc[i][1] + b1v;
            o.z = acc[i][2] + b2v; o.w = acc[i][3] + b3v;
            *(float4*)&g_P[pbase + (size_t)m * 1024 + n0 + tx * 4] = o;
        }
    }
}

// ---------------- persistent LSTM recurrence ------------------------
// 128 blocks = 2 dirs * 16 j-tiles(16) * 4 batch-groups(32); 256 threads.
// thread = (b_local 0..31, jp 0..7): 1 batch, j-pair (f32x2 packed over j).
__global__ void __launch_bounds__(256, 1)
k_lstm(const float* __restrict__ Whf, const float* __restrict__ Whb,
       const int* __restrict__ lens, const int* __restrict__ wid)
{
    extern __shared__ float sm[];
    float* Wp  = sm;                       // 32 rows (g*8+jp) x 516 floats = 66048 B
    ull*   Hsh = (ull*)(sm + 16512);       // 32 rows x 258 ull (dup h)    = 66048 B

    const int tid = threadIdx.x;
    const int d   = blockIdx.x >> 6;
    const int rem = blockIdx.x & 63;
    const int jb  = rem >> 2, bg = rem & 3;
    const int j0  = jb * 16, b0 = bg * 32;
    const float* __restrict__ Whh = d ? Whb : Whf;
    const float* __restrict__ P   = g_P + (size_t)d * V * 1024;

    // W_hh tile -> shared, j-pair interleaved: Wp[(g*8+jp)*516 + k*2 + (j&1)]
    for (int idx = tid; idx < 16384; idx += 256) {
        int g = idx >> 12, j = (idx >> 8) & 15, k = idx & 255;
        Wp[(size_t)(g * 8 + (j >> 1)) * 516 + k * 2 + (j & 1)] =
            Whh[(size_t)(g * H + j0 + j) * H + k];
    }

    const int jp = tid & 7, bl = tid >> 3;
    const int bA = b0 + bl;
    const int jcol = j0 + jp * 2;
    int maxlen = 0;
    for (int i = 0; i < 32; i++) { int L = lens[b0 + i]; if (L > maxlen) maxlen = L; }
    const int LA = lens[bA];

    float c0 = 0.f, c1 = 0.f;
    unsigned* barp = &g_bar[d * 4 + bg];
    const ulonglong2* w0p = (const ulonglong2*)(Wp + (size_t)(jp)      * 516);
    const ulonglong2* w1p = (const ulonglong2*)(Wp + (size_t)(8 + jp)  * 516);
    const ulonglong2* w2p = (const ulonglong2*)(Wp + (size_t)(16 + jp) * 516);
    const ulonglong2* w3p = (const ulonglong2*)(Wp + (size_t)(24 + jp) * 516);
    const ulonglong2* hdp = (const ulonglong2*)(Hsh + (size_t)bl * 258);
    __syncthreads();

    for (int t = 0; t < maxlen; t++) {
        // ---- prefetch gate pre-activations (independent of barrier) ----
        float2 px0, px1, px2, px3;
        int pos = 0;
        const bool valid = (t < LA);
        if (valid) {
            pos = d ? (LA - 1 - t) : t;
            const float2* prow = (const float2*)(P + (size_t)wid[bA * T + pos] * 1024) + jp + j0 / 2;
            px0 = __ldg(prow);       px1 = __ldg(prow + 128);
            px2 = __ldg(prow + 256); px3 = __ldg(prow + 384);
        }

        // ---- wait for all blocks' h(t-1) ----
        if (tid == 0) {
            unsigned tgt = 16u * (unsigned)t;
            unsigned v;
            do { asm volatile("ld.acquire.gpu.global.u32 %0, [%1];" : "=r"(v) : "l"(barp) : "memory"); } while (v < tgt);
        }
        __syncthreads();
        __threadfence();

        // ---- load duplicated h tile (L2, bypass L1) ----
        const int rb = t & 1;
        const ull* hsrc = g_hdup + ((size_t)(rb * 2 + d) * B + b0) * 256;
        #pragma unroll
        for (int q = 0; q < 16; q++) {
            int i = tid + q * 256;
            int r = i >> 7, cc = i & 127;
            ulonglong2 hv = __ldcg((const ulonglong2*)(hsrc + (size_t)r * 256 + cc * 2));
            *((ulonglong2*)(Hsh + (size_t)r * 258 + cc * 2)) = hv;
        }
        __syncthreads();

        // ---- recurrent GEMM: pure LDS.128 -> fma2 ----
        ull a0 = 0ull, a1 = 0ull, a2 = 0ull, a3 = 0ull;
        #pragma unroll 4
        for (int k2 = 0; k2 < 128; k2++) {
            ulonglong2 w0 = w0p[k2];
            ulonglong2 w1 = w1p[k2];
            ulonglong2 w2 = w2p[k2];
            ulonglong2 w3 = w3p[k2];
            ulonglong2 hh = hdp[k2];
            a0 = fma2(w0.x, hh.x, a0);
            a1 = fma2(w1.x, hh.x, a1);
            a2 = fma2(w2.x, hh.x, a2);
            a3 = fma2(w3.x, hh.x, a3);
            a0 = fma2(w0.y, hh.y, a0);
            a1 = fma2(w1.y, hh.y, a1);
            a2 = fma2(w2.y, hh.y, a2);
            a3 = fma2(w3.y, hh.y, a3);
        }

        // ---- gates + publish ----
        const int wb = (t + 1) & 1;
        if (valid) {
            float gi0, gi1, gf0, gf1, gg0, gg1, go0, go1;
            unpack2(a0, gi0, gi1); unpack2(a1, gf0, gf1);
            unpack2(a2, gg0, gg1); unpack2(a3, go0, go1);
            float i0 = sigf (gi0 + px0.x), i1 = sigf (gi1 + px0.y);
            float f0 = sigf (gf0 + px1.x), f1 = sigf (gf1 + px1.y);
            float g0 = tanhf(gg0 + px2.x), g1 = tanhf(gg1 + px2.y);
            float o0 = sigf (go0 + px3.x), o1 = sigf (go1 + px3.y);
            c0 = f0 * c0 + i0 * g0;
            c1 = f1 * c1 + i1 * g1;
            float h0 = o0 * tanhf(c0), h1 = o1 * tanhf(c1);
            ulonglong2 hdv; hdv.x = pack2(h0, h0); hdv.y = pack2(h1, h1);
            *((ulonglong2*)(g_hdup + ((size_t)(wb * 2 + d) * B + bA) * 256 + jcol)) = hdv;
            float2 hv; hv.x = h0; hv.y = h1;
            *(float2*)&g_Hc[((size_t)bA * T + pos) * (2 * H) + d * H + jcol] = hv;
        }

        // ---- arrive ----
        __threadfence();
        __syncthreads();
        if (tid == 0)
            asm volatile("red.release.gpu.global.add.u32 [%0], %1;" :: "l"(barp), "r"(1u) : "memory");
    }
}

// ---------------- attention scores: s = tanh(Hc W_s1^T) W_s2^T ------
// 512 threads, 32 t-rows of one b; W_s1 packed as f32x2 a-pairs in shared.
__global__ void k_scores(const float* __restrict__ Ws1, const float* __restrict__ Ws2)
{
    extern __shared__ char s2raw[];
    ull*   Wsp = (ull*)s2raw;                 // [13][512]  53248 B
    float* raw = (float*)(s2raw + 53248);     // [32][25]
    float* usm = raw + 32 * DA;               // [32][25]

    const int tid = threadIdx.x;
    const int b  = blockIdx.x >> 4;
    const int t0 = (blockIdx.x & 15) * 32;

    for (int i = tid; i < 13 * 512; i += 512) {
        int p = i >> 9, k = i & 511;
        float lo = Ws1[(size_t)(2 * p) * 512 + k];
        float hi = (p < 12) ? Ws1[(size_t)(2 * p + 1) * 512 + k] : 0.0f;
        Wsp[i] = pack2(lo, hi);
    }
    __syncthreads();

    const int wp = tid >> 5, lane = tid & 31;   // warp wp -> rows 2wp, 2wp+1
    const float* hc0 = g_Hc + ((size_t)b * T + t0 + wp * 2) * 512;
    ull acc0[13] = {}, acc1[13] = {};
    #pragma unroll 4
    for (int kk = 0; kk < 16; kk++) {
        int k = lane + kk * 32;
        float h0 = hc0[k];
        float h1 = hc0[512 + k];
        ull hd0 = pack2(h0, h0), hd1 = pack2(h1, h1);
        #pragma unroll
        for (int p = 0; p < 13; p++) {
            ull w = Wsp[p * 512 + k];
            acc0[p] = fma2(w, hd0, acc0[p]);
            acc1[p] = fma2(w, hd1, acc1[p]);
        }
    }
    #pragma unroll
    for (int p = 0; p < 13; p++) {
        ull v0 = acc0[p], v1 = acc1[p];
        #pragma unroll
        for (int off = 16; off; off >>= 1) {
            v0 = add2(v0, __shfl_xor_sync(0xffffffffu, v0, off));
            v1 = add2(v1, __shfl_xor_sync(0xffffffffu, v1, off));
        }
        if (lane == 0) {
            float x, y;
            unpack2(v0, x, y);
            raw[(wp * 2 + 0) * DA + 2 * p] = x;
            if (p < 12) raw[(wp * 2 + 0) * DA + 2 * p + 1] = y;
            unpack2(v1, x, y);
            raw[(wp * 2 + 1) * DA + 2 * p] = x;
            if (p < 12) raw[(wp * 2 + 1) * DA + 2 * p + 1] = y;
        }
    }
    __syncthreads();
    for (int i = tid; i < 32 * DA; i += 512) usm[i] = tanhf(raw[i]);
    __syncthreads();
    if (tid < 32 * HEADS) {
        int r = tid / HEADS, h = tid % HEADS;
        float s = 0.f;
        #pragma unroll
        for (int a = 0; a < DA; a++) s = fmaf(usm[r * DA + a], __ldg(&Ws2[h * DA + a]), s);
        g_s[((size_t)b * HEADS + h) * T + t0 + r] = s;
    }
}

// ---------------- masked softmax over time, per (b,head) ------------
__global__ void k_softmax(const int* __restrict__ lens)
{
    int b = blockIdx.x / HEADS, h = blockIdx.x % HEADS;
    int t = threadIdx.x;               // 512
    int L = lens[b];
    __shared__ float red[512];
    float sv = (t < L) ? g_s[((size_t)b * HEADS + h) * T + t] : -3.0e38f;
    red[t] = sv; __syncthreads();
    for (int off = 256; off; off >>= 1) { if (t < off) red[t] = fmaxf(red[t], red[t + off]); __syncthreads(); }
    float m = red[0]; __syncthreads();
    float e = (t < L) ? expf(sv - m) : 0.0f;
    red[t] = e; __syncthreads();
    for (int off = 256; off; off >>= 1) { if (t < off) red[t] += red[t + off]; __syncthreads(); }
    g_A[((size_t)b * HEADS + h) * T + t] = e / red[0];
}

// ---------------- M = A @ Hc  ->  sentence embeddings ---------------
__global__ void k_M(float* __restrict__ out)
{
    int b = blockIdx.x;
    int d = threadIdx.x;               // 512
    __shared__ float As[HEADS * T];
    for (int i = d; i < HEADS * T; i += 512) As[i] = g_A[(size_t)b * HEADS * T + i];
    __syncthreads();
    float acc[HEADS] = {};
    const float* hcb = g_Hc + (size_t)b * T * 512;
    for (int t = 0; t < T; t++) {
        float hc = hcb[(size_t)t * 512 + d];
        #pragma unroll
        for (int h = 0; h < HEADS; h++) acc[h] = fmaf(As[h * T + t], hc, acc[h]);
    }
    #pragma unroll
    for (int h = 0; h < HEADS; h++)
        out[(size_t)b * (HEADS * 2 * H) + h * 512 + d] = acc[h];
}

// ---------------- penalty -------------------------------------------
__global__ void k_penal1()
{
    int b = blockIdx.x;
    int tid = threadIdx.x;             // 256
    __shared__ float As[HEADS * T];
    __shared__ float red[256];
    for (int i = tid; i < HEADS * T; i += 256) As[i] = g_A[(size_t)b * HEADS * T + i];
    __syncthreads();
    float tot = 0.0f;
    for (int h = 0; h < HEADS; h++) {
        for (int g = 0; g < HEADS; g++) {
            if (h == g) continue;
            float p = 0.0f;
            for (int t = tid; t < T; t += 256) p = fmaf(As[h * T + t], As[g * T + t], p);
            red[tid] = p; __syncthreads();
            for (int off = 128; off; off >>= 1) { if (tid < off) red[tid] += red[tid + off]; __syncthreads(); }
            if (tid == 0) tot += red[0] * red[0];
            __syncthreads();
        }
    }
    if (tid == 0) g_pp[b] = tot;
}

__global__ void k_penal2(float* __restrict__ out, int out_size)
{
    __shared__ float red[128];
    red[threadIdx.x] = g_pp[threadIdx.x];
    __syncthreads();
    for (int off = 64; off; off >>= 1) { if (threadIdx.x < off) red[threadIdx.x] += red[threadIdx.x + off]; __syncthreads(); }
    if (threadIdx.x == 0) out[out_size - 1] = red[0] / (float)B;
}

// ---------------- launch --------------------------------------------
extern "C" void kernel_launch(void* const* d_in, const int* in_sizes, int n_in,
                              void* d_out, int out_size)
{
    const int*   word_ids = (const int*)  d_in[0];
    const int*   lens     = (const int*)  d_in[1];
    const float* emb      = (const float*)d_in[2];
    const float* Wihf     = (const float*)d_in[3];
    const float* Whhf     = (const float*)d_in[4];
    const float* bf       = (const float*)d_in[5];
    const float* Wihb     = (const float*)d_in[6];
    const float* Whhb     = (const float*)d_in[7];
    const float* bb       = (const float*)d_in[8];
    const float* Ws1      = (const float*)d_in[9];
    const float* Ws2      = (const float*)d_in[10];
    float* out = (float*)d_out;

    k_init<<<64, 256>>>();

    dim3 gP(16, (V + 63) / 64, 2);
    k_P<<<gP, 256>>>(emb, Wihf, bf, Wihb, bb);

    cudaFuncSetAttribute(k_lstm, cudaFuncAttributeMaxDynamicSharedMemorySize, 132096);
    k_lstm<<<128, 256, 132096>>>(Whhf, Whhb, lens, word_ids);

    cudaFuncSetAttribute(k_scores, cudaFuncAttributeMaxDynamicSharedMemorySize, 59648);
    k_scores<<<(B * T) / 32, 512, 59648>>>(Ws1, Ws2);

    k_softmax<<<B * HEADS, 512>>>(lens);
    k_M<<<B, 512>>>(out);
    k_penal1<<<B, 256>>>();
    k_penal2<<<1, 128>>>(out, out_size);
}

// round 5
// speedup vs baseline: 1.5484x; 1.5484x over previous
#include <cuda_runtime.h>
#include <math.h>
#include <stdint.h>

#define B 128
#define T 512
#define E 256
#define H 256
#define DA 25
#define HEADS 5
#define V 2080

typedef unsigned long long ull;

// ---------------- device scratch (static, no allocs) ----------------
__device__ float g_P[(size_t)2 * V * 1024];        // [dir][v][4H]  17MB (L2-resident)
__device__ float g_hstate[2 * 2 * B * H];          // [buf][dir][b][H]
__device__ float g_Hc[(size_t)B * T * 2 * H];      // [b][t][512]; tail stale-but-finite, masked by A=0
__device__ float g_s[B * HEADS * T];               // [b][h][t]
__device__ float g_A[B * HEADS * T];               // [b][h][t]
__device__ float g_pp[B];
__device__ unsigned g_bar[8];

__device__ __forceinline__ float sigf(float x) { return 1.0f / (1.0f + expf(-x)); }

__device__ __forceinline__ ull pack2(float lo, float hi) {
    ull r; asm("mov.b64 %0, {%1,%2};" : "=l"(r) : "f"(lo), "f"(hi)); return r;
}
__device__ __forceinline__ void unpack2(ull v, float& lo, float& hi) {
    asm("mov.b64 {%0,%1}, %2;" : "=f"(lo), "=f"(hi) : "l"(v));
}
__device__ __forceinline__ ull fma2(ull a, ull b, ull c) {
    ull d; asm("fma.rn.f32x2 %0, %1, %2, %3;" : "=l"(d) : "l"(a), "l"(b), "l"(c)); return d;
}
__device__ __forceinline__ ull add2(ull a, ull b) {
    ull d; asm("add.rn.f32x2 %0, %1, %2;" : "=l"(d) : "l"(a), "l"(b)); return d;
}

// ---------------- init: zero h buffers + barriers --------------------
__global__ void k_init() {
    size_t i = (size_t)blockIdx.x * blockDim.x + threadIdx.x;
    size_t stride = (size_t)gridDim.x * blockDim.x;
    for (size_t p = i; p < (size_t)2 * 2 * B * H; p += stride) g_hstate[p] = 0.0f;
    if (i < 8) g_bar[i] = 0u;
}

// ---------------- vocab projection: P[d][v][n] = emb[v] . W_ih[n] + b[n]
__global__ void k_P(const float* __restrict__ emb,
                    const float* __restrict__ Wf, const float* __restrict__ bf,
                    const float* __restrict__ Wb, const float* __restrict__ bb)
{
    const int d = blockIdx.z;
    const float* __restrict__ Wih  = d ? Wb : Wf;
    const float* __restrict__ bias = d ? bb : bf;
    const int n0 = blockIdx.x * 64;
    const int m0 = blockIdx.y * 64;

    __shared__ float As[16][68];
    __shared__ float Bs[16][68];

    const int tid = threadIdx.x;
    const int r  = tid >> 2, kq = tid & 3;
    const int tx = tid & 15, ty = tid >> 4;
    int v = m0 + r; if (v >= V) v = 0;
    const float* __restrict__ Arow = emb + (size_t)v * E;
    const float* __restrict__ Brow = Wih + (size_t)(n0 + r) * E;

    float acc[4][4] = {};

    for (int k0 = 0; k0 < E; k0 += 16) {
        float4 av = *(const float4*)&Arow[k0 + kq * 4];
        float4 bv = *(const float4*)&Brow[k0 + kq * 4];
        As[kq * 4 + 0][r] = av.x; As[kq * 4 + 1][r] = av.y;
        As[kq * 4 + 2][r] = av.z; As[kq * 4 + 3][r] = av.w;
        Bs[kq * 4 + 0][r] = bv.x; Bs[kq * 4 + 1][r] = bv.y;
        Bs[kq * 4 + 2][r] = bv.z; Bs[kq * 4 + 3][r] = bv.w;
        __syncthreads();
        #pragma unroll
        for (int kk = 0; kk < 16; kk++) {
            float4 a  = *(const float4*)&As[kk][ty * 4];
            float4 b4 = *(const float4*)&Bs[kk][tx * 4];
            acc[0][0] = fmaf(a.x, b4.x, acc[0][0]); acc[0][1] = fmaf(a.x, b4.y, acc[0][1]);
            acc[0][2] = fmaf(a.x, b4.z, acc[0][2]); acc[0][3] = fmaf(a.x, b4.w, acc[0][3]);
            acc[1][0] = fmaf(a.y, b4.x, acc[1][0]); acc[1][1] = fmaf(a.y, b4.y, acc[1][1]);
            acc[1][2] = fmaf(a.y, b4.z, acc[1][2]); acc[1][3] = fmaf(a.y, b4.w, acc[1][3]);
            acc[2][0] = fmaf(a.z, b4.x, acc[2][0]); acc[2][1] = fmaf(a.z, b4.y, acc[2][1]);
            acc[2][2] = fmaf(a.z, b4.z, acc[2][2]); acc[2][3] = fmaf(a.z, b4.w, acc[2][3]);
            acc[3][0] = fmaf(a.w, b4.x, acc[3][0]); acc[3][1] = fmaf(a.w, b4.y, acc[3][1]);
            acc[3][2] = fmaf(a.w, b4.z, acc[3][2]); acc[3][3] = fmaf(a.w, b4.w, acc[3][3]);
        }
        __syncthreads();
    }

    float b0v = bias[n0 + tx * 4 + 0];
    float b1v = bias[n0 + tx * 4 + 1];
    float b2v = bias[n0 + tx * 4 + 2];
    float b3v = bias[n0 + tx * 4 + 3];
    const size_t pbase = (size_t)d * V * 1024;
    #pragma unroll
    for (int i = 0; i < 4; i++) {
        int m = m0 + ty * 4 + i;
        if (m < V) {
            float4 o;
            o.x = acc[i][0] + b0v; o.y = acc[i][1] + b1v;
            o.z = acc[i][2] + b2v; o.w = acc[i][3] + b3v;
            *(float4*)&g_P[pbase + (size_t)m * 1024 + n0 + tx * 4] = o;
        }
    }
}

// ---------------- persistent LSTM recurrence ------------------------
// 128 blocks = 2 dirs * 16 j-tiles(16) * 4 batch-groups(32); 256 threads.
// thread = (kh, jp 0..7, bq 0..15): k-half split, 2 batches, j-pair (f32x2 over j).
__global__ void __launch_bounds__(256, 1)
k_lstm(const float* __restrict__ Whf, const float* __restrict__ Whb,
       const int* __restrict__ lens, const int* __restrict__ wid)
{
    extern __shared__ float sm[];
    float* Wp  = sm;                         // 16512 floats (66048 B)
    float* Hsh = sm + 16512;                 // 8320 floats  (33280 B)
    ull*   Red = (ull*)(sm + 24832);         // [128][10] ull (10240 B)

    const int tid = threadIdx.x;
    const int d   = blockIdx.x >> 6;
    const int rem = blockIdx.x & 63;
    const int jb  = rem >> 2, bg = rem & 3;
    const int j0  = jb * 16, b0 = bg * 32;
    const float* __restrict__ Whh = d ? Whb : Whf;
    const float* __restrict__ P   = g_P + (size_t)d * V * 1024;

    // W_hh tile -> shared, j-pair interleaved: Wp[(g*8+jp)*516 + k*2 + (j&1)]
    for (int idx = tid; idx < 16384; idx += 256) {
        int g = idx >> 12, j = (idx >> 8) & 15, k = idx & 255;
        Wp[(size_t)(g * 8 + (j >> 1)) * 516 + k * 2 + (j & 1)] =
            Whh[(size_t)(g * H + j0 + j) * H + k];
    }

    const int kh = tid >> 7;               // k-half: 0 -> k[0,128), 1 -> k[128,256)
    const int tl = tid & 127;
    const int jp = tl & 7, bq = tl >> 3;
    const int bA = b0 + bq * 2, bB = bA + 1;
    const int jcol = j0 + jp * 2;
    int maxlen = 0;
    for (int i = 0; i < 32; i++) { int L = lens[b0 + i]; if (L > maxlen) maxlen = L; }
    const int LA = lens[bA], LB = lens[bB];

    float cA0 = 0.f, cA1 = 0.f, cB0 = 0.f, cB1 = 0.f;
    const unsigned barid = d * 4 + bg;

    const ulonglong2* w0p = (const ulonglong2*)(Wp + (size_t)(jp)      * 516 + kh * 256);
    const ulonglong2* w1p = (const ulonglong2*)(Wp + (size_t)(8 + jp)  * 516 + kh * 256);
    const ulonglong2* w2p = (const ulonglong2*)(Wp + (size_t)(16 + jp) * 516 + kh * 256);
    const ulonglong2* w3p = (const ulonglong2*)(Wp + (size_t)(24 + jp) * 516 + kh * 256);
    const float2* hAp = (const float2*)(Hsh + (size_t)(bq * 2)     * 260 + kh * 128);
    const float2* hBp = (const float2*)(Hsh + (size_t)(bq * 2 + 1) * 260 + kh * 128);
    __syncthreads();

    for (int t = 0; t < maxlen; t++) {
        // ---- prefetch gate pre-activations (kh==0 threads do the epilogue) ----
        float2 pxA0, pxA1, pxA2, pxA3, pxB0, pxB1, pxB2, pxB3;
        int posA = 0, posB = 0;
        const bool vA = (t < LA), vB = (t < LB);
        if (kh == 0) {
            if (vA) {
                posA = d ? (LA - 1 - t) : t;
                const float2* p = (const float2*)(P + (size_t)wid[bA * T + posA] * 1024) + (j0 >> 1) + jp;
                pxA0 = __ldg(p); pxA1 = __ldg(p + 128); pxA2 = __ldg(p + 256); pxA3 = __ldg(p + 384);
            }
            if (vB) {
                posB = d ? (LB - 1 - t) : t;
                const float2* p = (const float2*)(P + (size_t)wid[bB * T + posB] * 1024) + (j0 >> 1) + jp;
                pxB0 = __ldg(p); pxB1 = __ldg(p + 128); pxB2 = __ldg(p + 256); pxB3 = __ldg(p + 384);
            }
        }

        // ---- h tile -> shared ----
        const int rb = t & 1;
        const float* hsrc = g_hstate + ((size_t)(rb * 2 + d) * B + b0) * H;
        #pragma unroll
        for (int q = 0; q < 8; q++) {
            int i = tid + q * 256; int r = i >> 6, cc = i & 63;
            float4 hv = __ldcg((const float4*)(hsrc + r * H + cc * 4));
            *(float4*)&Hsh[r * 260 + cc * 4] = hv;
        }
        __syncthreads();

        // ---- partial recurrent GEMM over this thread's k-half ----
        ull a00 = 0, a01 = 0, a10 = 0, a11 = 0, a20 = 0, a21 = 0, a30 = 0, a31 = 0;
        #pragma unroll 4
        for (int k2 = 0; k2 < 64; k2++) {
            ulonglong2 w0 = w0p[k2];
            ulonglong2 w1 = w1p[k2];
            ulonglong2 w2 = w2p[k2];
            ulonglong2 w3 = w3p[k2];
            float2 hA = hAp[k2];
            float2 hB = hBp[k2];
            ull hA0 = pack2(hA.x, hA.x), hA1 = pack2(hA.y, hA.y);
            ull hB0 = pack2(hB.x, hB.x), hB1 = pack2(hB.y, hB.y);
            a00 = fma2(w0.x, hA0, a00);
            a10 = fma2(w1.x, hA0, a10);
            a20 = fma2(w2.x, hA0, a20);
            a30 = fma2(w3.x, hA0, a30);
            a01 = fma2(w0.x, hB0, a01);
            a11 = fma2(w1.x, hB0, a11);
            a21 = fma2(w2.x, hB0, a21);
            a31 = fma2(w3.x, hB0, a31);
            a00 = fma2(w0.y, hA1, a00);
            a10 = fma2(w1.y, hA1, a10);
            a20 = fma2(w2.y, hA1, a20);
            a30 = fma2(w3.y, hA1, a30);
            a01 = fma2(w0.y, hB1, a01);
            a11 = fma2(w1.y, hB1, a11);
            a21 = fma2(w2.y, hB1, a21);
            a31 = fma2(w3.y, hB1, a31);
        }

        // ---- cross-half reduction ----
        if (kh) {
            ulonglong2* rp = (ulonglong2*)(Red + (size_t)tl * 10);
            ulonglong2 v0; v0.x = a00; v0.y = a01;
            ulonglong2 v1; v1.x = a10; v1.y = a11;
            ulonglong2 v2; v2.x = a20; v2.y = a21;
            ulonglong2 v3; v3.x = a30; v3.y = a31;
            rp[0] = v0; rp[1] = v1; rp[2] = v2; rp[3] = v3;
        }
        __syncthreads();

        // ---- gates + publish (kh==0 only) ----
        const int wb = (t + 1) & 1;
        if (kh == 0) {
            const ulonglong2* rp = (const ulonglong2*)(Red + (size_t)tl * 10);
            ulonglong2 r0 = rp[0], r1 = rp[1], r2 = rp[2], r3 = rp[3];
            a00 = add2(a00, r0.x); a01 = add2(a01, r0.y);
            a10 = add2(a10, r1.x); a11 = add2(a11, r1.y);
            a20 = add2(a20, r2.x); a21 = add2(a21, r2.y);
            a30 = add2(a30, r3.x); a31 = add2(a31, r3.y);

            if (vA) {
                float gi0, gi1, gf0, gf1, gg0, gg1, go0, go1;
                unpack2(a00, gi0, gi1); unpack2(a10, gf0, gf1);
                unpack2(a20, gg0, gg1); unpack2(a30, go0, go1);
                float i0 = sigf (gi0 + pxA0.x), i1 = sigf (gi1 + pxA0.y);
                float f0 = sigf (gf0 + pxA1.x), f1 = sigf (gf1 + pxA1.y);
                float g0 = tanhf(gg0 + pxA2.x), g1 = tanhf(gg1 + pxA2.y);
                float o0 = sigf (go0 + pxA3.x), o1 = sigf (go1 + pxA3.y);
                cA0 = f0 * cA0 + i0 * g0;
                cA1 = f1 * cA1 + i1 * g1;
                float2 hv; hv.x = o0 * tanhf(cA0); hv.y = o1 * tanhf(cA1);
                *(float2*)&g_hstate[((size_t)(wb * 2 + d) * B + bA) * H + jcol] = hv;
                *(float2*)&g_Hc[((size_t)bA * T + posA) * (2 * H) + d * H + jcol] = hv;
            }
            if (vB) {
                float gi0, gi1, gf0, gf1, gg0, gg1, go0, go1;
                unpack2(a01, gi0, gi1); unpack2(a11, gf0, gf1);
                unpack2(a21, gg0, gg1); unpack2(a31, go0, go1);
                float i0 = sigf (gi0 + pxB0.x), i1 = sigf (gi1 + pxB0.y);
                float f0 = sigf (gf0 + pxB1.x), f1 = sigf (gf1 + pxB1.y);
                float g0 = tanhf(gg0 + pxB2.x), g1 = tanhf(gg1 + pxB2.y);
                float o0 = sigf (go0 + pxB3.x), o1 = sigf (go1 + pxB3.y);
                cB0 = f0 * cB0 + i0 * g0;
                cB1 = f1 * cB1 + i1 * g1;
                float2 hv; hv.x = o0 * tanhf(cB0); hv.y = o1 * tanhf(cB1);
                *(float2*)&g_hstate[((size_t)(wb * 2 + d) * B + bB) * H + jcol] = hv;
                *(float2*)&g_Hc[((size_t)bB * T + posB) * (2 * H) + d * H + jcol] = hv;
            }
        }

        // ---- inter-block barrier (round-3 proven form) ----
        __threadfence();
        __syncthreads();
        if (tid == 0) {
            atomicAdd(&g_bar[barid], 1u);
            unsigned target = 16u * (unsigned)(t + 1);
            while (*((volatile unsigned*)&g_bar[barid]) < target) {}
            __threadfence();
        }
        __syncthreads();
    }
}

// ---------------- attention scores: s = tanh(Hc W_s1^T) W_s2^T ------
// block: 512 threads, 32 t-rows of one b; W_s1 in shared. (round-3 proven)
__global__ void k_scores(const float* __restrict__ Ws1, const float* __restrict__ Ws2)
{
    extern __shared__ float s2[];
    float* Ws  = s2;            // 25*512 = 12800
    float* raw = s2 + 12800;    // 32*25 = 800
    float* usm = s2 + 13600;    // 800

    const int tid = threadIdx.x;
    const int b  = blockIdx.x >> 4;
    const int t0 = (blockIdx.x & 15) * 32;

    for (int i = tid; i < 12800; i += 512) Ws[i] = Ws1[i];
    __syncthreads();

    const int wp = tid >> 5, lane = tid & 31;   // warp wp -> rows 2wp, 2wp+1
    float acc0[DA] = {}, acc1[DA] = {};
    const float* hc0 = g_Hc + ((size_t)b * T + t0 + wp * 2) * 512;
    #pragma unroll 4
    for (int kk = 0; kk < 16; kk++) {
        int k = lane + kk * 32;
        float h0 = hc0[k];
        float h1 = hc0[512 + k];
        #pragma unroll
        for (int a = 0; a < DA; a++) {
            float w = Ws[a * 512 + k];
            acc0[a] = fmaf(h0, w, acc0[a]);
            acc1[a] = fmaf(h1, w, acc1[a]);
        }
    }
    #pragma unroll
    for (int a = 0; a < DA; a++) {
        float v0 = acc0[a], v1 = acc1[a];
        #pragma unroll
        for (int off = 16; off; off >>= 1) {
            v0 += __shfl_xor_sync(0xffffffffu, v0, off);
            v1 += __shfl_xor_sync(0xffffffffu, v1, off);
        }
        if (lane == 0) {
            raw[(wp * 2 + 0) * DA + a] = v0;
            raw[(wp * 2 + 1) * DA + a] = v1;
        }
    }
    __syncthreads();
    for (int i = tid; i < 32 * DA; i += 512) usm[i] = tanhf(raw[i]);
    __syncthreads();
    if (tid < 32 * HEADS) {
        int r = tid / HEADS, h = tid % HEADS;
        float s = 0.f;
        #pragma unroll
        for (int a = 0; a < DA; a++) s = fmaf(usm[r * DA + a], __ldg(&Ws2[h * DA + a]), s);
        g_s[((size_t)b * HEADS + h) * T + t0 + r] = s;
    }
}

// ---------------- masked softmax over time, per (b,head) ------------
__global__ void k_softmax(const int* __restrict__ lens)
{
    int b = blockIdx.x / HEADS, h = blockIdx.x % HEADS;
    int t = threadIdx.x;               // 512
    int L = lens[b];
    __shared__ float red[512];
    float sv = (t < L) ? g_s[((size_t)b * HEADS + h) * T + t] : -3.0e38f;
    red[t] = sv; __syncthreads();
    for (int off = 256; off; off >>= 1) { if (t < off) red[t] = fmaxf(red[t], red[t + off]); __syncthreads(); }
    float m = red[0]; __syncthreads();
    float e = (t < L) ? expf(sv - m) : 0.0f;
    red[t] = e; __syncthreads();
    for (int off = 256; off; off >>= 1) { if (t < off) red[t] += red[t + off]; __syncthreads(); }
    g_A[((size_t)b * HEADS + h) * T + t] = e / red[0];
}

// ---------------- M = A @ Hc  ->  sentence embeddings ---------------
__global__ void k_M(float* __restrict__ out)
{
    int b = blockIdx.x;
    int d = threadIdx.x;               // 512
    __shared__ float As[HEADS * T];
    for (int i = d; i < HEADS * T; i += 512) As[i] = g_A[(size_t)b * HEADS * T + i];
    __syncthreads();
    float acc[HEADS] = {};
    const float* hcb = g_Hc + (size_t)b * T * 512;
    for (int t = 0; t < T; t++) {
        float hc = hcb[(size_t)t * 512 + d];
        #pragma unroll
        for (int h = 0; h < HEADS; h++) acc[h] = fmaf(As[h * T + t], hc, acc[h]);
    }
    #pragma unroll
    for (int h = 0; h < HEADS; h++)
        out[(size_t)b * (HEADS * 2 * H) + h * 512 + d] = acc[h];
}

// ---------------- penalty -------------------------------------------
__global__ void k_penal1()
{
    int b = blockIdx.x;
    int tid = threadIdx.x;             // 256
    __shared__ float As[HEADS * T];
    __shared__ float red[256];
    for (int i = tid; i < HEADS * T; i += 256) As[i] = g_A[(size_t)b * HEADS * T + i];
    __syncthreads();
    float tot = 0.0f;
    for (int h = 0; h < HEADS; h++) {
        for (int g = 0; g < HEADS; g++) {
            if (h == g) continue;
            float p = 0.0f;
            for (int t = tid; t < T; t += 256) p = fmaf(As[h * T + t], As[g * T + t], p);
            red[tid] = p; __syncthreads();
            for (int off = 128; off; off >>= 1) { if (tid < off) red[tid] += red[tid + off]; __syncthreads(); }
            if (tid == 0) tot += red[0] * red[0];
            __syncthreads();
        }
    }
    if (tid == 0) g_pp[b] = tot;
}

__global__ void k_penal2(float* __restrict__ out, int out_size)
{
    __shared__ float red[128];
    red[threadIdx.x] = g_pp[threadIdx.x];
    __syncthreads();
    for (int off = 64; off; off >>= 1) { if (threadIdx.x < off) red[threadIdx.x] += red[threadIdx.x + off]; __syncthreads(); }
    if (threadIdx.x == 0) out[out_size - 1] = red[0] / (float)B;
}

// ---------------- launch --------------------------------------------
extern "C" void kernel_launch(void* const* d_in, const int* in_sizes, int n_in,
                              void* d_out, int out_size)
{
    const int*   word_ids = (const int*)  d_in[0];
    const int*   lens     = (const int*)  d_in[1];
    const float* emb      = (const float*)d_in[2];
    const float* Wihf     = (const float*)d_in[3];
    const float* Whhf     = (const float*)d_in[4];
    const float* bf       = (const float*)d_in[5];
    const float* Wihb     = (const float*)d_in[6];
    const float* Whhb     = (const float*)d_in[7];
    const float* bb       = (const float*)d_in[8];
    const float* Ws1      = (const float*)d_in[9];
    const float* Ws2      = (const float*)d_in[10];
    float* out = (float*)d_out;

    k_init<<<64, 256>>>();

    dim3 gP(16, (V + 63) / 64, 2);
    k_P<<<gP, 256>>>(emb, Wihf, bf, Wihb, bb);

    cudaFuncSetAttribute(k_lstm, cudaFuncAttributeMaxDynamicSharedMemorySize, 109568);
    k_lstm<<<128, 256, 109568>>>(Whhf, Whhb, lens, word_ids);

    cudaFuncSetAttribute(k_scores, cudaFuncAttributeMaxDynamicSharedMemorySize, 57600);
    k_scores<<<(B * T) / 32, 512, 57600>>>(Ws1, Ws2);

    k_softmax<<<B * HEADS, 512>>>(lens);
    k_M<<<B, 512>>>(out);
    k_penal1<<<B, 256>>>();
    k_penal2<<<1, 128>>>(out, out_size);
}